// round 1
// baseline (speedup 1.0000x reference)
#include <cuda_runtime.h>

// Problem constants
#define B_  2048
#define T_  512
#define H_  128
#define NB  16      // batch elements per CTA
#define NCTA (B_/NB)  // 128 CTAs

// Persistent scratch (static device globals — no runtime allocation)
__device__ float  g_xt[T_ * B_];          // x transposed: [t][b], 4 MB
__device__ float2 g_Wp[4 * 64 * 128];     // [gate][k/2][j] -> (W[r][2k], W[r][2k+1]), 256 KB
__device__ float4 g_a4[H_];               // per-j input weights for gates (i,f,g,o)
__device__ float4 g_b4[H_];               // per-j combined bias (b_ih + b_hh) for (i,f,g,o)

// sm_103a packed dual-FMA (ptxas never emits this from C++; PTX-only)
__device__ __forceinline__ unsigned long long fma2(unsigned long long a,
                                                   unsigned long long b,
                                                   unsigned long long c) {
    unsigned long long d;
    asm("fma.rn.f32x2 %0, %1, %2, %3;" : "=l"(d) : "l"(a), "l"(b), "l"(c));
    return d;
}

__device__ __forceinline__ float sigf(float x)  { return 1.0f / (1.0f + __expf(-x)); }
__device__ __forceinline__ float tanhf_(float x){ return 2.0f / (1.0f + __expf(-2.0f * x)) - 1.0f; }

// ---------------- prep kernels ----------------

__global__ void prep_x(const float* __restrict__ x) {
    int idx = blockIdx.x * blockDim.x + threadIdx.x;
    if (idx < B_ * T_) {
        int b = idx / T_;
        int t = idx - b * T_;
        g_xt[t * B_ + b] = x[idx];
    }
}

__global__ void prep_w(const float* __restrict__ W_hh, const float* __restrict__ W_ih,
                       const float* __restrict__ b_ih, const float* __restrict__ b_hh) {
    int idx = blockIdx.x * blockDim.x + threadIdx.x;
    if (idx < 4 * 64 * 128) {
        int j  = idx & 127;
        int kp = (idx >> 7) & 63;
        int g  = idx >> 13;
        int r  = g * 128 + j;
        g_Wp[idx] = make_float2(W_hh[r * H_ + 2 * kp], W_hh[r * H_ + 2 * kp + 1]);
    }
    if (idx < H_) {
        g_a4[idx] = make_float4(W_ih[idx], W_ih[H_ + idx], W_ih[2 * H_ + idx], W_ih[3 * H_ + idx]);
        g_b4[idx] = make_float4(b_ih[idx]        + b_hh[idx],
                                b_ih[H_ + idx]   + b_hh[H_ + idx],
                                b_ih[2*H_ + idx] + b_hh[2*H_ + idx],
                                b_ih[3*H_ + idx] + b_hh[3*H_ + idx]);
    }
}

// ---------------- main persistent LSTM kernel ----------------
// Thread (rg = tid&127, bg = tid>>7) owns hidden unit j=rg, all 4 gates,
// batch elements [blockIdx.x*16 + 8*bg .. +7]. c state in registers,
// h carried in SMEM (layout [b][k], padded row so per-warp writes are
// bank-conflict-free and per-k reads are warp-broadcast LDS.64).

__global__ void __launch_bounds__(256, 1) lstm_main(
    const float* __restrict__ hx0, const float* __restrict__ cx0,
    const float* __restrict__ W_mlp, const float* __restrict__ b_mlp,
    float* __restrict__ out)
{
    __shared__ __align__(16) float h_s[NB][H_ + 2];  // row stride 130 floats (520 B: 8B-aligned pairs, bank-safe)
    __shared__ float xs[NB];

    const int tid   = threadIdx.x;
    const int rg    = tid & 127;          // hidden unit j
    const int bg    = tid >> 7;           // 0 or 1
    const int bbase = blockIdx.x * NB + bg * 8;

    const float4 a4 = g_a4[rg];
    const float4 b4 = g_b4[rg];

    float c[8];
#pragma unroll
    for (int i = 0; i < 8; i++) {
        c[i] = cx0[(bbase + i) * H_ + rg];
        h_s[bg * 8 + i][rg] = hx0[(bbase + i) * H_ + rg];
    }

    for (int t = 0; t < T_; t++) {
        if (tid < NB) xs[tid] = g_xt[t * B_ + blockIdx.x * NB + tid];
        __syncthreads();   // h_s(t-1) and xs(t) visible

        float xv[8];
#pragma unroll
        for (int i = 0; i < 8; i++) xv[i] = xs[bg * 8 + i];

        // acc[g][i] = f32x2 (even-k partial, odd-k partial) for gate-row g, batch i
        unsigned long long acc[4][8];
#pragma unroll
        for (int g = 0; g < 4; g++)
#pragma unroll
            for (int i = 0; i < 8; i++) acc[g][i] = 0ull;

#pragma unroll 2
        for (int kp = 0; kp < 64; kp++) {
            unsigned long long w[4];
#pragma unroll
            for (int g = 0; g < 4; g++)
                w[g] = *reinterpret_cast<const unsigned long long*>(&g_Wp[(g * 64 + kp) * 128 + rg]);
            unsigned long long hh[8];
#pragma unroll
            for (int i = 0; i < 8; i++)
                hh[i] = *reinterpret_cast<const unsigned long long*>(&h_s[bg * 8 + i][kp * 2]);
#pragma unroll
            for (int g = 0; g < 4; g++)
#pragma unroll
                for (int i = 0; i < 8; i++)
                    acc[g][i] = fma2(w[g], hh[i], acc[g][i]);
        }

        float hn[8];
#pragma unroll
        for (int i = 0; i < 8; i++) {
            float s[4];
#pragma unroll
            for (int g = 0; g < 4; g++) {
                unsigned long long v = acc[g][i];
                s[g] = __uint_as_float((unsigned)v) + __uint_as_float((unsigned)(v >> 32));
            }
            float zi = s[0] + b4.x + xv[i] * a4.x;
            float zf = s[1] + b4.y + xv[i] * a4.y;
            float zg = s[2] + b4.z + xv[i] * a4.z;
            float zo = s[3] + b4.w + xv[i] * a4.w;
            float ig = sigf(zi);
            float fg = sigf(zf);
            float gg = tanhf_(zg);
            float og = sigf(zo);
            float cn = fg * c[i] + ig * gg;
            c[i] = cn;
            hn[i] = og * tanhf_(cn);
        }

        __syncthreads();   // all k-loop reads of old h done
#pragma unroll
        for (int i = 0; i < 8; i++) h_s[bg * 8 + i][rg] = hn[i];
    }

    __syncthreads();
    // Final MLP + sigmoid: out[b] = sigmoid(h . W_mlp + b_mlp)
    if (tid < NB) {
        int b = blockIdx.x * NB + tid;
        float acc = b_mlp[0];
#pragma unroll 8
        for (int j = 0; j < H_; j++) acc += h_s[tid][j] * W_mlp[j];
        out[b] = sigf(acc);
    }
}

// ---------------- launch ----------------

extern "C" void kernel_launch(void* const* d_in, const int* in_sizes, int n_in,
                              void* d_out, int out_size) {
    (void)in_sizes; (void)n_in; (void)out_size;
    const float* x     = (const float*)d_in[0];
    const float* hx0   = (const float*)d_in[1];
    const float* cx0   = (const float*)d_in[2];
    const float* W_ih  = (const float*)d_in[3];
    const float* W_hh  = (const float*)d_in[4];
    const float* b_ih  = (const float*)d_in[5];
    const float* b_hh  = (const float*)d_in[6];
    const float* W_mlp = (const float*)d_in[7];
    const float* b_mlp = (const float*)d_in[8];
    float* out = (float*)d_out;

    prep_x<<<(B_ * T_ + 255) / 256, 256>>>(x);
    prep_w<<<(4 * 64 * 128 + 255) / 256, 256>>>(W_hh, W_ih, b_ih, b_hh);
    lstm_main<<<NCTA, 256>>>(hx0, cx0, W_mlp, b_mlp, out);
}

// round 4
// speedup vs baseline: 1.4119x; 1.4119x over previous
#include <cuda_runtime.h>

#define B_  2048
#define T_  512
#define H_  128
#define NB  16
#define NCTA (B_/NB)     // 128 CTAs, one wave on 148 SMs
#define KQ_RES 24        // kq < KQ_RES -> L1-resident (192KB); rest streams from L2 (64KB/step)
#define HSTRIDE (H_ + 4) // 132 floats = 528B row: 16B multiple, bank-safe

// Packed weights: g_Wq[(gate*32 + kq)*128 + j] = W_hh[r][4kq .. 4kq+3], r = gate*128+j
__device__ float4 g_Wq[4 * 32 * 128];   // 256 KB

// sm_103a packed dual-FMA (PTX-only; ptxas never auto-fuses)
__device__ __forceinline__ unsigned long long fma2(unsigned long long a,
                                                   unsigned long long b,
                                                   unsigned long long c) {
    unsigned long long d;
    asm("fma.rn.f32x2 %0, %1, %2, %3;" : "=l"(d) : "l"(a), "l"(b), "l"(c));
    return d;
}

// 16B weight loads with L1 eviction-priority control
__device__ __forceinline__ ulonglong2 ldg_resident(const float4* p) {
    ulonglong2 v;
    asm("ld.global.L1::evict_last.v2.b64 {%0, %1}, [%2];"
        : "=l"(v.x), "=l"(v.y) : "l"(p));
    return v;
}
__device__ __forceinline__ ulonglong2 ldg_stream(const float4* p) {
    ulonglong2 v;
    asm("ld.global.nc.L1::no_allocate.v2.b64 {%0, %1}, [%2];"
        : "=l"(v.x), "=l"(v.y) : "l"(p));
    return v;
}
__device__ __forceinline__ void stg_noalloc(float4* p, float4 v) {
    asm volatile("st.global.L1::no_allocate.v4.f32 [%0], {%1, %2, %3, %4};"
                 :: "l"(p), "f"(v.x), "f"(v.y), "f"(v.z), "f"(v.w) : "memory");
}

__device__ __forceinline__ float tanhx(float x) {
    float y; asm("tanh.approx.f32 %0, %1;" : "=f"(y) : "f"(x)); return y;
}
__device__ __forceinline__ float sigx(float x) {   // sigmoid via MUFU.TANH
    return fmaf(tanhx(0.5f * x), 0.5f, 0.5f);
}

__global__ void __launch_bounds__(256, 1) lstm_all(
    const float* __restrict__ x,    const float* __restrict__ hx0,
    const float* __restrict__ cx0,  const float* __restrict__ W_ih,
    const float* __restrict__ W_hh, const float* __restrict__ b_ih,
    const float* __restrict__ b_hh, const float* __restrict__ W_mlp,
    const float* __restrict__ b_mlp, float* __restrict__ out)
{
    __shared__ __align__(16) float h_s[NB][HSTRIDE];
    __shared__ float xs[NB];

    const int tid   = threadIdx.x;
    const int rg    = tid & 127;     // hidden unit j
    const int bg    = tid >> 7;      // batch half
    const int b0    = blockIdx.x * NB;
    const int bbase = b0 + bg * 8;

    // ---- Prep: every CTA writes the full packed weight array (identical values
    // from all CTAs -> benign duplicate writes; own-CTA order via __syncthreads).
    // no_allocate stores keep L1 clean for the resident read-set.
    for (int idx = tid; idx < 4 * 128 * 32; idx += 256) {
        int kq = idx & 31;            // k-quad (lanes sweep kq -> coalesced W_hh reads)
        int r  = idx >> 5;            // row 0..511
        int g  = r >> 7;
        int j  = r & 127;
        const float4 wv = *reinterpret_cast<const float4*>(&W_hh[r * H_ + 4 * kq]);
        stg_noalloc(&g_Wq[(g * 32 + kq) * 128 + j], wv);
    }

    // Per-thread input weights and combined bias for (i,f,g,o) of unit rg
    const float4 a4 = make_float4(W_ih[rg], W_ih[H_ + rg], W_ih[2*H_ + rg], W_ih[3*H_ + rg]);
    const float4 b4 = make_float4(b_ih[rg]        + b_hh[rg],
                                  b_ih[H_ + rg]   + b_hh[H_ + rg],
                                  b_ih[2*H_ + rg] + b_hh[2*H_ + rg],
                                  b_ih[3*H_ + rg] + b_hh[3*H_ + rg]);

    float c[8];
#pragma unroll
    for (int i = 0; i < 8; i++) {
        c[i] = cx0[(bbase + i) * H_ + rg];
        h_s[bg * 8 + i][rg] = hx0[(bbase + i) * H_ + rg];
    }
    __syncthreads();   // weights written (this CTA), h_s initialized

#pragma unroll 1
    for (int t = 0; t < T_; t++) {
        if (tid < NB) xs[tid] = x[(b0 + tid) * T_ + t];   // line reused over 32 steps
        __syncthreads();

        float xv[8];
#pragma unroll
        for (int i = 0; i < 8; i++) xv[i] = xs[bg * 8 + i];

        // acc[g][i] = f32x2 (even-k partial, odd-k partial)
        unsigned long long acc[4][8];
#pragma unroll
        for (int g = 0; g < 4; g++)
#pragma unroll
            for (int i = 0; i < 8; i++) acc[g][i] = 0ull;

        // --- L1-resident portion (192 KB, pinned via evict_last) ---
#pragma unroll 2
        for (int kq = 0; kq < KQ_RES; kq++) {
            ulonglong2 w[4];
#pragma unroll
            for (int g = 0; g < 4; g++)
                w[g] = ldg_resident(&g_Wq[(g * 32 + kq) * 128 + rg]);
            ulonglong2 hh[8];
#pragma unroll
            for (int i = 0; i < 8; i++)
                hh[i] = *reinterpret_cast<const ulonglong2*>(&h_s[bg * 8 + i][kq * 4]);
#pragma unroll
            for (int g = 0; g < 4; g++)
#pragma unroll
                for (int i = 0; i < 8; i++) {
                    acc[g][i] = fma2(w[g].x, hh[i].x, acc[g][i]);
                    acc[g][i] = fma2(w[g].y, hh[i].y, acc[g][i]);
                }
        }
        // --- streaming portion (64 KB/step from L2; never touches L1) ---
#pragma unroll 2
        for (int kq = KQ_RES; kq < 32; kq++) {
            ulonglong2 w[4];
#pragma unroll
            for (int g = 0; g < 4; g++)
                w[g] = ldg_stream(&g_Wq[(g * 32 + kq) * 128 + rg]);
            ulonglong2 hh[8];
#pragma unroll
            for (int i = 0; i < 8; i++)
                hh[i] = *reinterpret_cast<const ulonglong2*>(&h_s[bg * 8 + i][kq * 4]);
#pragma unroll
            for (int g = 0; g < 4; g++)
#pragma unroll
                for (int i = 0; i < 8; i++) {
                    acc[g][i] = fma2(w[g].x, hh[i].x, acc[g][i]);
                    acc[g][i] = fma2(w[g].y, hh[i].y, acc[g][i]);
                }
        }

        float hn[8];
#pragma unroll
        for (int i = 0; i < 8; i++) {
            float s[4];
#pragma unroll
            for (int g = 0; g < 4; g++) {
                unsigned long long v = acc[g][i];
                s[g] = __uint_as_float((unsigned)v) + __uint_as_float((unsigned)(v >> 32));
            }
            float zi = s[0] + b4.x + xv[i] * a4.x;
            float zf = s[1] + b4.y + xv[i] * a4.y;
            float zg = s[2] + b4.z + xv[i] * a4.z;
            float zo = s[3] + b4.w + xv[i] * a4.w;
            float ig = sigx(zi);
            float fg = sigx(zf);
            float gg = tanhx(zg);
            float og = sigx(zo);
            float cn = fg * c[i] + ig * gg;
            c[i] = cn;
            hn[i] = og * tanhx(cn);
        }

        __syncthreads();   // all reads of old h done
#pragma unroll
        for (int i = 0; i < 8; i++) h_s[bg * 8 + i][rg] = hn[i];
    }

    __syncthreads();
    // Final MLP + sigmoid: out[b] = sigmoid(h . W_mlp + b_mlp)
    if (tid < NB) {
        int b = b0 + tid;
        float acc = b_mlp[0];
#pragma unroll 8
        for (int j = 0; j < H_; j++) acc += h_s[tid][j] * W_mlp[j];
        out[b] = sigx(acc);
    }
}

extern "C" void kernel_launch(void* const* d_in, const int* in_sizes, int n_in,
                              void* d_out, int out_size) {
    (void)in_sizes; (void)n_in; (void)out_size;
    const float* x     = (const float*)d_in[0];
    const float* hx0   = (const float*)d_in[1];
    const float* cx0   = (const float*)d_in[2];
    const float* W_ih  = (const float*)d_in[3];
    const float* W_hh  = (const float*)d_in[4];
    const float* b_ih  = (const float*)d_in[5];
    const float* b_hh  = (const float*)d_in[6];
    const float* W_mlp = (const float*)d_in[7];
    const float* b_mlp = (const float*)d_in[8];
    float* out = (float*)d_out;

    lstm_all<<<NCTA, 256>>>(x, hx0, cx0, W_ih, W_hh, b_ih, b_hh, W_mlp, b_mlp, out);
}

// round 6
// speedup vs baseline: 1.4397x; 1.0197x over previous
#include <cuda_runtime.h>

#define B_  2048
#define T_  512
#define H_  128
#define NB  16
#define NCTA (B_/NB)     // 128 CTAs, one wave
#define HSTRIDE (H_ + 4) // 132 floats: 16B multiple, bank-safe

// Packed weights: g_Wq[(gate*32 + kq)*128 + j] = W_hh[r][4kq..4kq+3], r = gate*128+j
__device__ float4 g_Wq[4 * 32 * 128];   // 256 KB

__device__ __forceinline__ unsigned long long fma2(unsigned long long a,
                                                   unsigned long long b,
                                                   unsigned long long c) {
    unsigned long long d;
    asm("fma.rn.f32x2 %0, %1, %2, %3;" : "=l"(d) : "l"(a), "l"(b), "l"(c));
    return d;
}
__device__ __forceinline__ ulonglong2 ldg_resident(const float4* p) {
    ulonglong2 v;
    asm("ld.global.L1::evict_last.v2.b64 {%0, %1}, [%2];" : "=l"(v.x), "=l"(v.y) : "l"(p));
    return v;
}
__device__ __forceinline__ ulonglong2 ldg_stream(const float4* p) {
    ulonglong2 v;
    asm("ld.global.nc.L1::no_allocate.v2.b64 {%0, %1}, [%2];" : "=l"(v.x), "=l"(v.y) : "l"(p));
    return v;
}
__device__ __forceinline__ void stg_noalloc(float4* p, float4 v) {
    asm volatile("st.global.L1::no_allocate.v4.f32 [%0], {%1, %2, %3, %4};"
                 :: "l"(p), "f"(v.x), "f"(v.y), "f"(v.z), "f"(v.w) : "memory");
}
__device__ __forceinline__ float tanhx(float x) {
    float y; asm("tanh.approx.f32 %0, %1;" : "=f"(y) : "f"(x)); return y;
}
__device__ __forceinline__ float sigx(float x) { return fmaf(tanhx(0.5f * x), 0.5f, 0.5f); }

__global__ void __launch_bounds__(256, 1) lstm_all(
    const float* __restrict__ x,    const float* __restrict__ hx0,
    const float* __restrict__ cx0,  const float* __restrict__ W_ih,
    const float* __restrict__ W_hh, const float* __restrict__ b_ih,
    const float* __restrict__ b_hh, const float* __restrict__ W_mlp,
    const float* __restrict__ b_mlp, float* __restrict__ out)
{
    __shared__ __align__(16) float h_s[2][NB][HSTRIDE];  // double-buffered hidden state
    __shared__ float xs[2][NB];

    const int tid   = threadIdx.x;
    const int rg    = tid & 127;
    const int bg    = tid >> 7;
    const int b0    = blockIdx.x * NB;
    const int bbase = b0 + bg * 8;

    // ---- one-time weight pack (benign duplicate writes from all CTAs) ----
    for (int idx = tid; idx < 4 * 128 * 32; idx += 256) {
        int kq = idx & 31;
        int r  = idx >> 5;
        const float4 wv = *reinterpret_cast<const float4*>(&W_hh[r * H_ + 4 * kq]);
        stg_noalloc(&g_Wq[((r >> 7) * 32 + kq) * 128 + (r & 127)], wv);
    }

    const float4 a4 = make_float4(W_ih[rg], W_ih[H_ + rg], W_ih[2*H_ + rg], W_ih[3*H_ + rg]);
    const float4 b4 = make_float4(b_ih[rg]        + b_hh[rg],
                                  b_ih[H_ + rg]   + b_hh[H_ + rg],
                                  b_ih[2*H_ + rg] + b_hh[2*H_ + rg],
                                  b_ih[3*H_ + rg] + b_hh[3*H_ + rg]);

    float c[8];
#pragma unroll
    for (int i = 0; i < 8; i++) {
        c[i] = cx0[(bbase + i) * H_ + rg];
        h_s[0][bg * 8 + i][rg] = hx0[(bbase + i) * H_ + rg];
    }
    if (tid < NB) xs[0][tid] = x[(b0 + tid) * T_ + 0];
    __syncthreads();

    const float4* wb = &g_Wq[rg];   // + (g*32+kq)*128 for gate g, quad kq

    // 64 FFMA2 on buffers W,HH into acc
#define FMABLK(W, HH)                                              \
    _Pragma("unroll")                                              \
    for (int g = 0; g < 4; g++)                                    \
        _Pragma("unroll")                                          \
        for (int i = 0; i < 8; i++) {                              \
            acc[g][i] = fma2(W[g].x, HH[i].x, acc[g][i]);          \
            acc[g][i] = fma2(W[g].y, HH[i].y, acc[g][i]);          \
        }
#define LDW_RES(W, KQ)                                             \
    _Pragma("unroll")                                              \
    for (int g = 0; g < 4; g++) W[g] = ldg_resident(wb + (g * 32 + (KQ)) * 128);
#define LDW_STR(W, KQ)                                             \
    _Pragma("unroll")                                              \
    for (int g = 0; g < 4; g++) W[g] = ldg_stream(wb + (g * 32 + (KQ)) * 128);
#define LDH(HH, P, KQ)                                             \
    _Pragma("unroll")                                              \
    for (int i = 0; i < 8; i++)                                    \
        HH[i] = *reinterpret_cast<const ulonglong2*>(&h_s[P][bg * 8 + i][(KQ) * 4]);

    ulonglong2 wA[4], wB[4], hA[8], hB[8];
    LDW_RES(wA, 0);     // steady-state invariant: wA holds kq=0 at loop head

    int p = 0;
#pragma unroll 1
    for (int t = 0; t < T_; t++) {
        // prefetch next step's x into the other xs buffer (line reused 32 steps)
        if (tid < NB) {
            int tn = (t + 1 < T_) ? t + 1 : t;
            xs[p ^ 1][tid] = x[(b0 + tid) * T_ + tn];
        }
        float xv[8];
#pragma unroll
        for (int i = 0; i < 8; i++) xv[i] = xs[p][bg * 8 + i];

        unsigned long long acc[4][8];
#pragma unroll
        for (int g = 0; g < 4; g++)
#pragma unroll
            for (int i = 0; i < 8; i++) acc[g][i] = 0ull;

        LDH(hA, p, 0);

        // resident region: pairs kqp=0..10 -> FMAs kq 0..21, lookahead loads to kq 22
#pragma unroll 1
        for (int kqp = 0; kqp < 11; kqp++) {
            int k0 = 2 * kqp;
            LDW_RES(wB, k0 + 1);  LDH(hB, p, k0 + 1);
            FMABLK(wA, hA);
            LDW_RES(wA, k0 + 2);  LDH(hA, p, k0 + 2);
            FMABLK(wB, hB);
        }
        // boundary pair: FMA kq 22,23; lookahead kq 24 switches to streaming
        {
            LDW_RES(wB, 23);  LDH(hB, p, 23);
            FMABLK(wA, hA);
            LDW_STR(wA, 24);  LDH(hA, p, 24);
            FMABLK(wB, hB);
        }
        // streaming region: pairs kqp=12..14 -> FMAs kq 24..29, lookahead to kq 30
#pragma unroll 1
        for (int kqp = 12; kqp < 15; kqp++) {
            int k0 = 2 * kqp;
            LDW_STR(wB, k0 + 1);  LDH(hB, p, k0 + 1);
            FMABLK(wA, hA);
            LDW_STR(wA, k0 + 2);  LDH(hA, p, k0 + 2);
            FMABLK(wB, hB);
        }
        // tail pair: FMA kq 30,31; prefetch NEXT STEP's kq=0 weights before epilogue
        {
            LDW_STR(wB, 31);  LDH(hB, p, 31);
            FMABLK(wA, hA);
            LDW_RES(wA, 0);                 // flies during epilogue MUFUs + barrier
            FMABLK(wB, hB);
        }

        // epilogue
        float hn[8];
#pragma unroll
        for (int i = 0; i < 8; i++) {
            float s[4];
#pragma unroll
            for (int g = 0; g < 4; g++) {
                unsigned long long v = acc[g][i];
                s[g] = __uint_as_float((unsigned)v) + __uint_as_float((unsigned)(v >> 32));
            }
            float zi = s[0] + b4.x + xv[i] * a4.x;
            float zf = s[1] + b4.y + xv[i] * a4.y;
            float zg = s[2] + b4.z + xv[i] * a4.z;
            float zo = s[3] + b4.w + xv[i] * a4.w;
            float ig = sigx(zi);
            float fg = sigx(zf);
            float gg = tanhx(zg);
            float og = sigx(zo);
            float cn = fg * c[i] + ig * gg;
            c[i] = cn;
            hn[i] = og * tanhx(cn);
        }

#pragma unroll
        for (int i = 0; i < 8; i++) h_s[p ^ 1][bg * 8 + i][rg] = hn[i];
        __syncthreads();     // single barrier per step
        p ^= 1;
    }

    // final MLP + sigmoid
    if (tid < NB) {
        int b = b0 + tid;
        float acc = b_mlp[0];
#pragma unroll 8
        for (int j = 0; j < H_; j++) acc += h_s[p][tid][j] * W_mlp[j];
        out[b] = sigx(acc);
    }
}

extern "C" void kernel_launch(void* const* d_in, const int* in_sizes, int n_in,
                              void* d_out, int out_size) {
    (void)in_sizes; (void)n_in; (void)out_size;
    const float* x     = (const float*)d_in[0];
    const float* hx0   = (const float*)d_in[1];
    const float* cx0   = (const float*)d_in[2];
    const float* W_ih  = (const float*)d_in[3];
    const float* W_hh  = (const float*)d_in[4];
    const float* b_ih  = (const float*)d_in[5];
    const float* b_hh  = (const float*)d_in[6];
    const float* W_mlp = (const float*)d_in[7];
    const float* b_mlp = (const float*)d_in[8];
    float* out = (float*)d_out;

    lstm_all<<<NCTA, 256>>>(x, hx0, cx0, W_ih, W_hh, b_ih, b_hh, W_mlp, b_mlp, out);
}